// round 12
// baseline (speedup 1.0000x reference)
#include <cuda_runtime.h>
#include <cstdint>

// Fixed shapes: pooled/indices [4,64,32,32,32], out [4,64,64,64,64]
#define NCHAN 256
#define POOL_PER_CHAN 32768
#define S_TOTAL 262144.0f

#define GRID 1184              // 148 SMs x 8 blocks: exactly one resident wave
#define NTILE 16384            // unpool tiles (256 threads x 16 outputs each)
#define NCHUNK 4096            // gating chunks: 16 slots/channel, 2048 floats each

__device__ float    d_partial[NCHUNK];
__device__ unsigned d_arrive;   // grid-barrier arrival counter (zero-init)
__device__ unsigned d_exit;     // exit tally for counter reset    (zero-init)

// ---------------------------------------------------------------------------
// Persistent fused kernel. ALL blocks resident (launch_bounds guarantees
// 8 blocks/SM: regs<=32, smem ~64B, 2048 thr/SM), so the software grid
// barrier between phases is deadlock-free.
// ---------------------------------------------------------------------------
__global__ __launch_bounds__(256, 8) void fused_kernel(const float* __restrict__ pooled,
                                                       const int*   __restrict__ indices,
                                                       float*       __restrict__ out) {
    const int tid  = threadIdx.x;
    const int lane = tid & 31;
    const int wid  = tid >> 5;
    __shared__ float sh[8];
    __shared__ float gsh;

    // ---------------- Phase 1: gating partials (silu-sum) ----------------
    // Chunk c covers floats [c*2048, (c+1)*2048): channel c>>4, slot c&15.
    for (unsigned c = blockIdx.x; c < NCHUNK; c += GRID) {
        const float* p = pooled + (size_t)c * 2048 + tid * 8;
        float v0, v1, v2, v3, v4, v5, v6, v7;
        asm volatile("ld.global.nc.v8.f32 {%0,%1,%2,%3,%4,%5,%6,%7}, [%8];"
                     : "=f"(v0), "=f"(v1), "=f"(v2), "=f"(v3),
                       "=f"(v4), "=f"(v5), "=f"(v6), "=f"(v7)
                     : "l"(p));
        float s = 0.0f;
        s += v0 * (1.0f / (1.0f + __expf(-v0)));
        s += v1 * (1.0f / (1.0f + __expf(-v1)));
        s += v2 * (1.0f / (1.0f + __expf(-v2)));
        s += v3 * (1.0f / (1.0f + __expf(-v3)));
        s += v4 * (1.0f / (1.0f + __expf(-v4)));
        s += v5 * (1.0f / (1.0f + __expf(-v5)));
        s += v6 * (1.0f / (1.0f + __expf(-v6)));
        s += v7 * (1.0f / (1.0f + __expf(-v7)));

        #pragma unroll
        for (int off = 16; off > 0; off >>= 1)
            s += __shfl_xor_sync(0xFFFFFFFFu, s, off);
        if (lane == 0) sh[wid] = s;
        __syncthreads();
        if (tid == 0) {
            float t = sh[0];
            #pragma unroll
            for (int j = 1; j < 8; j++) t += sh[j];
            d_partial[c] = t;                       // fixed slot: deterministic
        }
        __syncthreads();
    }

    // ---------------- Grid barrier (all blocks resident => safe) ----------
    if (tid == 0) {
        __threadfence();                            // release partials
        atomicAdd(&d_arrive, 1u);
        volatile unsigned* va = &d_arrive;
        while (*va < GRID) { __nanosleep(64); }
        __threadfence();                            // acquire all partials
    }
    __syncthreads();

    // ---------------- Phase 2: dense unpool + gate -------------------------
    // Tile t == old blockIdx: u layout [bc(8) | d0(6) | ho(6) | wo16(2)].
    for (unsigned t = blockIdx.x; t < NTILE; t += GRID) {
        const unsigned bc = t >> 6;

        const unsigned u  = t * 256u + tid;
        const unsigned wo = (u & 3u) << 4;          // 0,16,32,48
        const unsigned ho = (u >> 2) & 63u;
        const unsigned d0 = (u >> 8) & 63u;

        const unsigned pbase = bc * POOL_PER_CHAN + (d0 >> 1) * 1024u
                             + (ho >> 1) * 32u + (wo >> 1);

        // Front-issue loads (L2-resident pooled after phase 1).
        const int4   ia = __ldg(reinterpret_cast<const int4*>(indices + pbase));
        const int4   ib = __ldg(reinterpret_cast<const int4*>(indices + pbase + 4));
        const float4 pa = __ldg(reinterpret_cast<const float4*>(pooled + pbase));
        const float4 pb = __ldg(reinterpret_cast<const float4*>(pooled + pbase + 4));

        // Finalize gating for this channel: 16 fixed-slot partials, warp 0.
        if (wid == 0) {
            float v = (lane < 16) ? d_partial[(bc << 4) + lane] : 0.0f;
            v += __shfl_xor_sync(0xFFFFFFFFu, v, 8);
            v += __shfl_xor_sync(0xFFFFFFFFu, v, 4);
            v += __shfl_xor_sync(0xFFFFFFFFu, v, 2);
            v += __shfl_xor_sync(0xFFFFFFFFu, v, 1);
            if (lane == 0) {
                float m = v / S_TOTAL;
                gsh = fminf(m, 0.0f) - log1pf(__expf(-fabsf(m)));  // log_sigmoid
            }
        }
        __syncthreads();
        const float g = gsh;

        const int base = (int)((d0 * 64u + ho) * 64u + wo);

        const float a0 = pa.x * g, a1 = pa.y * g, a2 = pa.z * g, a3 = pa.w * g;
        const float b0 = pb.x * g, b1 = pb.y * g, b2 = pb.z * g, b3 = pb.w * g;

        float o0  = (ia.x == base +  0) ? a0 : 0.0f;
        float o1  = (ia.x == base +  1) ? a0 : 0.0f;
        float o2  = (ia.y == base +  2) ? a1 : 0.0f;
        float o3  = (ia.y == base +  3) ? a1 : 0.0f;
        float o4  = (ia.z == base +  4) ? a2 : 0.0f;
        float o5  = (ia.z == base +  5) ? a2 : 0.0f;
        float o6  = (ia.w == base +  6) ? a3 : 0.0f;
        float o7  = (ia.w == base +  7) ? a3 : 0.0f;
        float o8  = (ib.x == base +  8) ? b0 : 0.0f;
        float o9  = (ib.x == base +  9) ? b0 : 0.0f;
        float o10 = (ib.y == base + 10) ? b1 : 0.0f;
        float o11 = (ib.y == base + 11) ? b1 : 0.0f;
        float o12 = (ib.z == base + 12) ? b2 : 0.0f;
        float o13 = (ib.z == base + 13) ? b2 : 0.0f;
        float o14 = (ib.w == base + 14) ? b3 : 0.0f;
        float o15 = (ib.w == base + 15) ? b3 : 0.0f;

        float* optr = out + 16ull * u;              // 64B-aligned
        asm volatile(
            "st.global.v8.f32 [%0], {%1, %2, %3, %4, %5, %6, %7, %8};"
            :: "l"(optr),
               "f"(o0), "f"(o1), "f"(o2), "f"(o3),
               "f"(o4), "f"(o5), "f"(o6), "f"(o7)
            : "memory");
        asm volatile(
            "st.global.v8.f32 [%0], {%1, %2, %3, %4, %5, %6, %7, %8};"
            :: "l"(optr + 8),
               "f"(o8),  "f"(o9),  "f"(o10), "f"(o11),
               "f"(o12), "f"(o13), "f"(o14), "f"(o15)
            : "memory");

        __syncthreads();                            // gsh reused next tile
    }

    // ---------------- Reset barrier counters for next graph replay --------
    if (tid == 0) {
        unsigned old = atomicAdd(&d_exit, 1u);
        if (old == GRID - 1) {                      // last block to finish
            d_arrive = 0;
            d_exit   = 0;
            __threadfence();
        }
    }
}

// ---------------------------------------------------------------------------
extern "C" void kernel_launch(void* const* d_in, const int* in_sizes, int n_in,
                              void* d_out, int out_size) {
    const float* pooled  = (const float*)d_in[0];
    const int*   indices = (const int*)d_in[1];
    float*       out     = (float*)d_out;

    fused_kernel<<<GRID, 256>>>(pooled, indices, out);
}

// round 14
// speedup vs baseline: 1.2368x; 1.2368x over previous
#include <cuda_runtime.h>
#include <cstdint>

// Fixed shapes: pooled/indices [4,64,32,32,32], out [4,64,64,64,64]
#define NCHAN 256
#define POOL_PER_CHAN 32768
#define SLOTS 8
#define S_TOTAL 262144.0f

__device__ float d_partial[NCHAN * SLOTS];

// ---------------------------------------------------------------------------
// Kernel 1 (primary): partial sum(silu(pooled)), 2048 blocks x 256 thr.
// Two 256-bit loads per thread, front-batched. PLC trigger at entry.
// (This kernel is byte-identical to the R11 version that measured 59.5us.)
// ---------------------------------------------------------------------------
__global__ __launch_bounds__(256) void gating_partial(const float* __restrict__ pooled) {
    cudaTriggerProgrammaticLaunchCompletion();

    const float* p = pooled + (size_t)blockIdx.x * 4096 + threadIdx.x * 8;

    float v0, v1, v2, v3, v4, v5, v6, v7;
    float w0, w1, w2, w3, w4, w5, w6, w7;
    asm volatile("ld.global.nc.v8.f32 {%0,%1,%2,%3,%4,%5,%6,%7}, [%8];"
                 : "=f"(v0), "=f"(v1), "=f"(v2), "=f"(v3),
                   "=f"(v4), "=f"(v5), "=f"(v6), "=f"(v7)
                 : "l"(p));
    asm volatile("ld.global.nc.v8.f32 {%0,%1,%2,%3,%4,%5,%6,%7}, [%8];"
                 : "=f"(w0), "=f"(w1), "=f"(w2), "=f"(w3),
                   "=f"(w4), "=f"(w5), "=f"(w6), "=f"(w7)
                 : "l"(p + 2048));

    float s = 0.0f;
    s += v0 * (1.0f / (1.0f + __expf(-v0)));
    s += v1 * (1.0f / (1.0f + __expf(-v1)));
    s += v2 * (1.0f / (1.0f + __expf(-v2)));
    s += v3 * (1.0f / (1.0f + __expf(-v3)));
    s += v4 * (1.0f / (1.0f + __expf(-v4)));
    s += v5 * (1.0f / (1.0f + __expf(-v5)));
    s += v6 * (1.0f / (1.0f + __expf(-v6)));
    s += v7 * (1.0f / (1.0f + __expf(-v7)));
    s += w0 * (1.0f / (1.0f + __expf(-w0)));
    s += w1 * (1.0f / (1.0f + __expf(-w1)));
    s += w2 * (1.0f / (1.0f + __expf(-w2)));
    s += w3 * (1.0f / (1.0f + __expf(-w3)));
    s += w4 * (1.0f / (1.0f + __expf(-w4)));
    s += w5 * (1.0f / (1.0f + __expf(-w5)));
    s += w6 * (1.0f / (1.0f + __expf(-w6)));
    s += w7 * (1.0f / (1.0f + __expf(-w7)));

    #pragma unroll
    for (int off = 16; off > 0; off >>= 1)
        s += __shfl_xor_sync(0xFFFFFFFFu, s, off);

    __shared__ float sh[8];
    const int lane = threadIdx.x & 31;
    const int wid  = threadIdx.x >> 5;
    if (lane == 0) sh[wid] = s;
    __syncthreads();
    if (threadIdx.x == 0) {
        float t = sh[0];
        #pragma unroll
        for (int j = 1; j < 8; j++) t += sh[j];
        d_partial[blockIdx.x] = t;     // slot = bc*8 + sub (fixed, deterministic)
    }
}

// ---------------------------------------------------------------------------
// Kernel 2 (PSS secondary): dense unpool + gate. 16 outputs/thread.
// 2x256-bit loads (both via the PROVEN v8.f32 form; index bits reinterpreted
// with __float_as_int — identical bytes), two 256-bit stores.
// u (16-output index) layout: [bc(8) | d0(6) | ho(6) | wo16(2)]
// ---------------------------------------------------------------------------
__global__ __launch_bounds__(256) void unpool_kernel(const float* __restrict__ pooled,
                                                     const int*   __restrict__ indices,
                                                     float*       __restrict__ out) {
    const unsigned bc = blockIdx.x >> 6;           // 64 blocks per channel

    const unsigned u  = blockIdx.x * 256u + threadIdx.x;
    const unsigned wo = (u & 3u) << 4;             // 0,16,32,48
    const unsigned ho = (u >> 2) & 63u;
    const unsigned d0 = (u >> 8) & 63u;

    const unsigned pbase = bc * POOL_PER_CHAN + (d0 >> 1) * 1024u + (ho >> 1) * 32u + (wo >> 1);

    // Front-issue both 256-bit loads (independent of the gating grid).
    float f0, f1, f2, f3, f4, f5, f6, f7;          // index bits as f32 regs
    float p0, p1, p2, p3, p4, p5, p6, p7;
    asm volatile("ld.global.nc.v8.f32 {%0,%1,%2,%3,%4,%5,%6,%7}, [%8];"
                 : "=f"(f0), "=f"(f1), "=f"(f2), "=f"(f3),
                   "=f"(f4), "=f"(f5), "=f"(f6), "=f"(f7)
                 : "l"(reinterpret_cast<const float*>(indices + pbase)));
    asm volatile("ld.global.nc.v8.f32 {%0,%1,%2,%3,%4,%5,%6,%7}, [%8];"
                 : "=f"(p0), "=f"(p1), "=f"(p2), "=f"(p3),
                   "=f"(p4), "=f"(p5), "=f"(p6), "=f"(p7)
                 : "l"(pooled + pbase));

    // Wait for gating grid completion (PDL dependency point).
    cudaGridDependencySynchronize();

    __shared__ float gsh;
    if (threadIdx.x == 0) {
        const float* pp = d_partial + bc * SLOTS;
        float t = 0.0f;
        #pragma unroll
        for (int j = 0; j < SLOTS; j++) t += pp[j];   // fixed order: deterministic
        float m = t / S_TOTAL;
        gsh = fminf(m, 0.0f) - log1pf(__expf(-fabsf(m)));   // log_sigmoid(m)
    }
    __syncthreads();
    const float g = gsh;

    const int i0 = __float_as_int(f0), i1 = __float_as_int(f1);
    const int i2 = __float_as_int(f2), i3 = __float_as_int(f3);
    const int i4 = __float_as_int(f4), i5 = __float_as_int(f5);
    const int i6 = __float_as_int(f6), i7 = __float_as_int(f7);

    const int base = (int)((d0 * 64u + ho) * 64u + wo);

    const float a0 = p0 * g, a1 = p1 * g, a2 = p2 * g, a3 = p3 * g;
    const float b0 = p4 * g, b1 = p5 * g, b2 = p6 * g, b3 = p7 * g;

    float o0  = (i0 == base +  0) ? a0 : 0.0f;
    float o1  = (i0 == base +  1) ? a0 : 0.0f;
    float o2  = (i1 == base +  2) ? a1 : 0.0f;
    float o3  = (i1 == base +  3) ? a1 : 0.0f;
    float o4  = (i2 == base +  4) ? a2 : 0.0f;
    float o5  = (i2 == base +  5) ? a2 : 0.0f;
    float o6  = (i3 == base +  6) ? a3 : 0.0f;
    float o7  = (i3 == base +  7) ? a3 : 0.0f;
    float o8  = (i4 == base +  8) ? b0 : 0.0f;
    float o9  = (i4 == base +  9) ? b0 : 0.0f;
    float o10 = (i5 == base + 10) ? b1 : 0.0f;
    float o11 = (i5 == base + 11) ? b1 : 0.0f;
    float o12 = (i6 == base + 12) ? b2 : 0.0f;
    float o13 = (i6 == base + 13) ? b2 : 0.0f;
    float o14 = (i7 == base + 14) ? b3 : 0.0f;
    float o15 = (i7 == base + 15) ? b3 : 0.0f;

    float* optr = out + 16ull * u;                 // 64B-aligned
    asm volatile(
        "st.global.v8.f32 [%0], {%1, %2, %3, %4, %5, %6, %7, %8};"
        :: "l"(optr),
           "f"(o0), "f"(o1), "f"(o2), "f"(o3),
           "f"(o4), "f"(o5), "f"(o6), "f"(o7)
        : "memory");
    asm volatile(
        "st.global.v8.f32 [%0], {%1, %2, %3, %4, %5, %6, %7, %8};"
        :: "l"(optr + 8),
           "f"(o8),  "f"(o9),  "f"(o10), "f"(o11),
           "f"(o12), "f"(o13), "f"(o14), "f"(o15)
        : "memory");
}

// ---------------------------------------------------------------------------
extern "C" void kernel_launch(void* const* d_in, const int* in_sizes, int n_in,
                              void* d_out, int out_size) {
    const float* pooled  = (const float*)d_in[0];
    const int*   indices = (const int*)d_in[1];
    float*       out     = (float*)d_out;

    gating_partial<<<NCHAN * SLOTS, 256>>>(pooled);          // 2048 blocks

    // Secondary launch with Programmatic Stream Serialization (proven R11
    // structure, 59.5us total).
    cudaLaunchConfig_t cfg = {};
    cfg.gridDim  = dim3(16384, 1, 1);
    cfg.blockDim = dim3(256, 1, 1);
    cfg.dynamicSmemBytes = 0;
    cfg.stream = 0;
    cudaLaunchAttribute attr[1];
    attr[0].id = cudaLaunchAttributeProgrammaticStreamSerialization;
    attr[0].val.programmaticStreamSerializationAllowed = 1;
    cfg.attrs = attr;
    cfg.numAttrs = 1;
    cudaLaunchKernelEx(&cfg, unpool_kernel, pooled, indices, out);
}